// round 11
// baseline (speedup 1.0000x reference)
#include <cuda_runtime.h>

// out = x * (1 + softmax(leaky(semantic@W1^T + b1)@W2^T + b2))
// x: [B=8, C=256, H=256, W=256] fp32.
// Gate kernel + persistent balanced scale kernel, overlapped via PDL.

#define B 8
#define C 256
#define HW4 16384                     // float4 per (b,c) plane (= 2^14)
#define TOT4 (B * C * HW4)            // 33,554,432 float4 total
#define NT 256
#define NBLK2 1184                    // 148 SMs * 8 blocks — zero tail wave
#define STRIDE (NBLK2 * NT)           // 303,104
#define PREF 4

__device__ float g_gate[B * C];

// ---------------------------------------------------------------------------
// Gate kernel: 8 blocks x 1024 threads. Warp-reduced float4 GEMVs + softmax.
// ---------------------------------------------------------------------------
__global__ __launch_bounds__(1024)
void gate_kernel(const float* __restrict__ semantic,
                 const float* __restrict__ W1, const float* __restrict__ b1,
                 const float* __restrict__ W2, const float* __restrict__ b2)
{
    __shared__ float sem[C];
    __shared__ float hbuf[C];
    __shared__ float lbuf[C];
    __shared__ float red[8];

    const int b    = blockIdx.x;
    const int t    = threadIdx.x;      // 0..1023
    const int lane = t & 31;
    const int warp = t >> 5;           // 0..31

    if (t < C) sem[t] = semantic[b * C + t];
    __syncthreads();

    const float4* sem4 = (const float4*)sem;
    const float4 s0 = sem4[lane];
    const float4 s1 = sem4[lane + 32];

    // stage 1: h = leaky(semantic @ W1^T + b1); 8 channels per warp
    #pragma unroll
    for (int i = 0; i < 8; i++) {
        const int c = warp * 8 + i;
        const float4* w4 = (const float4*)(W1 + c * C);
        const float4 a0 = w4[lane];
        const float4 a1 = w4[lane + 32];
        float d = a0.x*s0.x + a0.y*s0.y + a0.z*s0.z + a0.w*s0.w
                + a1.x*s1.x + a1.y*s1.y + a1.z*s1.z + a1.w*s1.w;
        #pragma unroll
        for (int o = 16; o > 0; o >>= 1) d += __shfl_xor_sync(0xFFFFFFFFu, d, o);
        if (lane == 0) { float h = d + b1[c]; hbuf[c] = (h > 0.f) ? h : 0.1f * h; }
    }
    __syncthreads();

    const float4* h4 = (const float4*)hbuf;
    const float4 h0 = h4[lane];
    const float4 h1 = h4[lane + 32];

    // stage 2: logits = h @ W2^T + b2
    #pragma unroll
    for (int i = 0; i < 8; i++) {
        const int c = warp * 8 + i;
        const float4* w4 = (const float4*)(W2 + c * C);
        const float4 a0 = w4[lane];
        const float4 a1 = w4[lane + 32];
        float d = a0.x*h0.x + a0.y*h0.y + a0.z*h0.z + a0.w*h0.w
                + a1.x*h1.x + a1.y*h1.y + a1.z*h1.z + a1.w*h1.w;
        #pragma unroll
        for (int o = 16; o > 0; o >>= 1) d += __shfl_xor_sync(0xFFFFFFFFu, d, o);
        if (lane == 0) lbuf[c] = d + b2[c];
    }
    __syncthreads();

    // softmax over 256 logits (threads 0..255)
    if (t < C) {
        float m = lbuf[t];
        #pragma unroll
        for (int o = 16; o > 0; o >>= 1) m = fmaxf(m, __shfl_xor_sync(0xFFFFFFFFu, m, o));
        if (lane == 0) red[warp] = m;
    }
    __syncthreads();
    if (t < 32) {
        float v = (lane < 8) ? red[lane] : -3.4e38f;
        #pragma unroll
        for (int o = 16; o > 0; o >>= 1) v = fmaxf(v, __shfl_xor_sync(0xFFFFFFFFu, v, o));
        if (lane == 0) red[0] = v;
    }
    __syncthreads();
    const float gmax = red[0];
    __syncthreads();

    float e = 0.f;
    if (t < C) {
        e = __expf(lbuf[t] - gmax);
        float s = e;
        #pragma unroll
        for (int o = 16; o > 0; o >>= 1) s += __shfl_xor_sync(0xFFFFFFFFu, s, o);
        if (lane == 0) red[warp] = s;
    }
    __syncthreads();
    if (t < 32) {
        float v = (lane < 8) ? red[lane] : 0.f;
        #pragma unroll
        for (int o = 16; o > 0; o >>= 1) v += __shfl_xor_sync(0xFFFFFFFFu, v, o);
        if (lane == 0) red[0] = v;
    }
    __syncthreads();

    if (t < C) g_gate[b * C + t] = 1.f + e / red[0];
    __threadfence();
    __syncthreads();

#if (__CUDA_ARCH__ >= 900)
    cudaTriggerProgrammaticLaunchCompletion();
#endif
}

// ---------------------------------------------------------------------------
// Scale kernel (PDL secondary): persistent, perfectly balanced grid-stride
// over the whole tensor. Plane index = i >> 14 (g_gate L1-hit broadcast).
// Register prefetch before gridDepSync overlaps the gate's execution.
// ---------------------------------------------------------------------------
__global__ __launch_bounds__(NT, 8)
void scale_kernel(const float4* __restrict__ x, float4* __restrict__ out)
{
    const unsigned i0 = blockIdx.x * NT + threadIdx.x;   // < STRIDE

    // prefetch PREF strided float4 before waiting on the gate kernel
    // (i0 + 3*STRIDE < 1.22M << TOT4, no bounds check needed)
    float4 buf[PREF];
    #pragma unroll
    for (int k = 0; k < PREF; k++) buf[k] = x[i0 + (unsigned)k * STRIDE];

#if (__CUDA_ARCH__ >= 900)
    cudaGridDependencySynchronize();
#endif

    unsigned i = i0;
    #pragma unroll
    for (int k = 0; k < PREF; k++) {
        const float s = g_gate[i >> 14];
        float4 v = buf[k];
        v.x *= s; v.y *= s; v.z *= s; v.w *= s;
        out[i] = v;
        i += STRIDE;
    }

    #pragma unroll 4
    for (; i < TOT4; i += STRIDE) {
        const float s = g_gate[i >> 14];
        float4 v = x[i];
        v.x *= s; v.y *= s; v.z *= s; v.w *= s;
        out[i] = v;
    }
}

extern "C" void kernel_launch(void* const* d_in, const int* in_sizes, int n_in,
                              void* d_out, int out_size) {
    const float* x        = (const float*)d_in[0];
    const float* semantic = (const float*)d_in[1];
    const float* W1       = (const float*)d_in[2];
    const float* b1       = (const float*)d_in[3];
    const float* W2       = (const float*)d_in[4];
    const float* b2       = (const float*)d_in[5];
    float* out = (float*)d_out;

    gate_kernel<<<B, 1024>>>(semantic, W1, b1, W2, b2);

    cudaLaunchConfig_t cfg = {};
    cfg.gridDim  = dim3(NBLK2);
    cfg.blockDim = dim3(NT);
    cfg.dynamicSmemBytes = 0;
    cfg.stream = 0;
    cudaLaunchAttribute attr[1];
    attr[0].id = cudaLaunchAttributeProgrammaticStreamSerialization;
    attr[0].val.programmaticStreamSerializationAllowed = 1;
    cfg.attrs = attr;
    cfg.numAttrs = 1;
    cudaLaunchKernelEx(&cfg, scale_kernel, (const float4*)x, (float4*)out);
}

// round 12
// speedup vs baseline: 1.1825x; 1.1825x over previous
#include <cuda_runtime.h>

// out = x * (1 + softmax(leaky(semantic@W1^T + b1)@W2^T + b2))
// x: [B=8, C=256, H=256, W=256] fp32.
// R2's per-plane streaming structure (verified 82% DRAM) + PDL overlap,
// plain loads (no ldcs/stcs — verified regression), plain-load prefetch.

#define B 8
#define C 256
#define HW4 16384            // float4 per (b,c) plane
#define NBLK (B * C)         // 2048 planes/blocks
#define NT 256
#define PREF 4               // float4 prefetched per thread before gridDepSync

__device__ float g_gate[B * C];

// ---------------------------------------------------------------------------
// Gate kernel: 8 blocks x 1024 threads. Warp-reduced float4 GEMVs + softmax.
// ---------------------------------------------------------------------------
__global__ __launch_bounds__(1024)
void gate_kernel(const float* __restrict__ semantic,
                 const float* __restrict__ W1, const float* __restrict__ b1,
                 const float* __restrict__ W2, const float* __restrict__ b2)
{
    __shared__ float sem[C];
    __shared__ float hbuf[C];
    __shared__ float lbuf[C];
    __shared__ float red[8];

    const int b    = blockIdx.x;
    const int t    = threadIdx.x;      // 0..1023
    const int lane = t & 31;
    const int warp = t >> 5;           // 0..31

    if (t < C) sem[t] = semantic[b * C + t];
    __syncthreads();

    const float4* sem4 = (const float4*)sem;
    const float4 s0 = sem4[lane];
    const float4 s1 = sem4[lane + 32];

    // stage 1: h = leaky(semantic @ W1^T + b1); 8 channels per warp
    #pragma unroll
    for (int i = 0; i < 8; i++) {
        const int c = warp * 8 + i;
        const float4* w4 = (const float4*)(W1 + c * C);
        const float4 a0 = w4[lane];
        const float4 a1 = w4[lane + 32];
        float d = a0.x*s0.x + a0.y*s0.y + a0.z*s0.z + a0.w*s0.w
                + a1.x*s1.x + a1.y*s1.y + a1.z*s1.z + a1.w*s1.w;
        #pragma unroll
        for (int o = 16; o > 0; o >>= 1) d += __shfl_xor_sync(0xFFFFFFFFu, d, o);
        if (lane == 0) { float h = d + b1[c]; hbuf[c] = (h > 0.f) ? h : 0.1f * h; }
    }
    __syncthreads();

    const float4* h4 = (const float4*)hbuf;
    const float4 h0 = h4[lane];
    const float4 h1 = h4[lane + 32];

    // stage 2: logits = h @ W2^T + b2
    #pragma unroll
    for (int i = 0; i < 8; i++) {
        const int c = warp * 8 + i;
        const float4* w4 = (const float4*)(W2 + c * C);
        const float4 a0 = w4[lane];
        const float4 a1 = w4[lane + 32];
        float d = a0.x*h0.x + a0.y*h0.y + a0.z*h0.z + a0.w*h0.w
                + a1.x*h1.x + a1.y*h1.y + a1.z*h1.z + a1.w*h1.w;
        #pragma unroll
        for (int o = 16; o > 0; o >>= 1) d += __shfl_xor_sync(0xFFFFFFFFu, d, o);
        if (lane == 0) lbuf[c] = d + b2[c];
    }
    __syncthreads();

    // softmax over 256 logits (threads 0..255)
    if (t < C) {
        float m = lbuf[t];
        #pragma unroll
        for (int o = 16; o > 0; o >>= 1) m = fmaxf(m, __shfl_xor_sync(0xFFFFFFFFu, m, o));
        if (lane == 0) red[warp] = m;
    }
    __syncthreads();
    if (t < 32) {
        float v = (lane < 8) ? red[lane] : -3.4e38f;
        #pragma unroll
        for (int o = 16; o > 0; o >>= 1) v = fmaxf(v, __shfl_xor_sync(0xFFFFFFFFu, v, o));
        if (lane == 0) red[0] = v;
    }
    __syncthreads();
    const float gmax = red[0];
    __syncthreads();

    float e = 0.f;
    if (t < C) {
        e = __expf(lbuf[t] - gmax);
        float s = e;
        #pragma unroll
        for (int o = 16; o > 0; o >>= 1) s += __shfl_xor_sync(0xFFFFFFFFu, s, o);
        if (lane == 0) red[warp] = s;
    }
    __syncthreads();
    if (t < 32) {
        float v = (lane < 8) ? red[lane] : 0.f;
        #pragma unroll
        for (int o = 16; o > 0; o >>= 1) v += __shfl_xor_sync(0xFFFFFFFFu, v, o);
        if (lane == 0) red[0] = v;
    }
    __syncthreads();

    if (t < C) g_gate[b * C + t] = 1.f + e / red[0];
    __threadfence();
    __syncthreads();

#if (__CUDA_ARCH__ >= 900)
    cudaTriggerProgrammaticLaunchCompletion();
#endif
}

// ---------------------------------------------------------------------------
// Scale kernel (PDL secondary): R2 structure — one block per contiguous
// (b,c) plane (1 MB each), plain loads/stores. PREF plain loads issued
// before gridDepSync to overlap the gate kernel.
// ---------------------------------------------------------------------------
__global__ __launch_bounds__(NT)
void scale_kernel(const float4* __restrict__ x, float4* __restrict__ out)
{
    const int plane = blockIdx.x;
    const int t     = threadIdx.x;
    const float4* xin = x + (size_t)plane * HW4;
    float4*       xo  = out + (size_t)plane * HW4;

    // overlap: first PREF loads issued before the dependency wait
    float4 buf[PREF];
    #pragma unroll
    for (int k = 0; k < PREF; k++) buf[k] = xin[t + k * NT];

#if (__CUDA_ARCH__ >= 900)
    cudaGridDependencySynchronize();
#endif
    const float s = g_gate[plane];

    #pragma unroll
    for (int k = 0; k < PREF; k++) {
        float4 v = buf[k];
        v.x *= s; v.y *= s; v.z *= s; v.w *= s;
        xo[t + k * NT] = v;
    }
    #pragma unroll 8
    for (int i = t + PREF * NT; i < HW4; i += NT) {
        float4 v = xin[i];
        v.x *= s; v.y *= s; v.z *= s; v.w *= s;
        xo[i] = v;
    }
}

extern "C" void kernel_launch(void* const* d_in, const int* in_sizes, int n_in,
                              void* d_out, int out_size) {
    const float* x        = (const float*)d_in[0];
    const float* semantic = (const float*)d_in[1];
    const float* W1       = (const float*)d_in[2];
    const float* b1       = (const float*)d_in[3];
    const float* W2       = (const float*)d_in[4];
    const float* b2       = (const float*)d_in[5];
    float* out = (float*)d_out;

    gate_kernel<<<B, 1024>>>(semantic, W1, b1, W2, b2);

    cudaLaunchConfig_t cfg = {};
    cfg.gridDim  = dim3(NBLK);
    cfg.blockDim = dim3(NT);
    cfg.dynamicSmemBytes = 0;
    cfg.stream = 0;
    cudaLaunchAttribute attr[1];
    attr[0].id = cudaLaunchAttributeProgrammaticStreamSerialization;
    attr[0].val.programmaticStreamSerializationAllowed = 1;
    cfg.attrs = attr;
    cfg.numAttrs = 1;
    cudaLaunchKernelEx(&cfg, scale_kernel, (const float4*)x, (float4*)out);
}